// round 6
// baseline (speedup 1.0000x reference)
#include <cuda_runtime.h>
#include <cuda_pipeline.h>
#include <math.h>

// ---------------- problem dims ----------------
#define NN   128
#define TT   16
#define DD   25
#define HH   256
#define HCC  512
#define HII  128
#define EE   128
#define HPP  256
#define LL   608          // D*(D-1)+8
#define KK   8
#define RKN  2
#define DHH  (DD*HH)      // 6400
#define P1KS 32           // split-K factor for e-GEMM
#define P1KC 200          // 6400/32
#define ONT  512          // ode_kernel threads

typedef unsigned long long u64;

// packed fp32x2 helpers (bit-identical to 2x FFMA)
__device__ __forceinline__ u64 pk2(float x) {
    u64 r; asm("mov.b64 %0, {%1, %1};" : "=l"(r) : "f"(x)); return r;
}
__device__ __forceinline__ void fma2(u64& d, u64 a, u64 b) {
    asm("fma.rn.f32x2 %0, %1, %2, %0;" : "+l"(d) : "l"(a), "l"(b));
}
__device__ __forceinline__ float2 up2(u64 p) {
    float2 v; asm("mov.b64 {%0, %1}, %2;" : "=f"(v.x), "=f"(v.y) : "l"(p)); return v;
}

// ---------------- persistent device scratch ----------------
__device__ float g_h     [NN*DHH];
__device__ float g_adj   [NN*DD*DD];
__device__ float g_epart [P1KS*NN*EE];
__device__ float g_e     [NN*EE];
__device__ float g_cat   [NN*2*EE];
__device__ float g_hq    [NN*HPP];
__device__ float g_logit [NN*LL];

// ---------------- helpers ----------------
__device__ __forceinline__ void cp_tile(float* dst, const float* src, int nf4,
                                        int tid, int nt) {
    const float4* s4 = (const float4*)src;
    float4* d4 = (float4*)dst;
    for (int p = tid; p < nf4; p += nt)
        __pipeline_memcpy_async(&d4[p], &s4[p], 16);
    __pipeline_commit();
}

__device__ __forceinline__ float blk_max256(float v, float* red, int tid) {
    red[tid] = v; __syncthreads();
    #pragma unroll
    for (int s = 128; s > 0; s >>= 1) {
        if (tid < s) red[tid] = fmaxf(red[tid], red[tid + s]);
        __syncthreads();
    }
    v = red[0]; __syncthreads();
    return v;
}
__device__ __forceinline__ float blk_sum256(float v, float* red, int tid) {
    red[tid] = v; __syncthreads();
    #pragma unroll
    for (int s = 128; s > 0; s >>= 1) {
        if (tid < s) red[tid] += red[tid + s];
        __syncthreads();
    }
    v = red[0]; __syncthreads();
    return v;
}

// ---------------- init h = broadcast(init_hstate) ----------------
__global__ void init_h_kernel(const float* __restrict__ ih) {
    int idx = blockIdx.x * blockDim.x + threadIdx.x;
    if (idx < NN*DHH) g_h[idx] = ih[idx % DHH];
}

// ---------------- P1: e partials, split-K GEMM  (128x6400 @ 6400x128) ------
__global__ __launch_bounds__(256)
void e_gemm_kernel(const float* __restrict__ wr)
{
    __shared__ float sa[8][64];
    __shared__ float sb[8][64];
    int tid = threadIdx.x;
    int tx = tid & 15, ty = tid >> 4;
    int rb = blockIdx.y * 64, cb = blockIdx.x * 64;
    int k0 = blockIdx.z * P1KC;

    float acc[4][4];
    #pragma unroll
    for (int i = 0; i < 4; i++)
        #pragma unroll
        for (int j = 0; j < 4; j++) acc[i][j] = 0.f;

    int r  = tid >> 2, kk  = (tid & 3) * 2;
    int k2 = tid >> 5, c2  = (tid & 31) * 2;

    for (int kb = 0; kb < P1KC; kb += 8) {
        float2 av = *(const float2*)&g_h[(size_t)(rb + r)*DHH + k0 + kb + kk];
        sa[kk][r] = av.x; sa[kk+1][r] = av.y;
        float2 wv = *(const float2*)&wr[(size_t)(k0 + kb + k2)*EE + cb + c2];
        sb[k2][c2] = wv.x; sb[k2][c2+1] = wv.y;
        __syncthreads();
        #pragma unroll
        for (int k = 0; k < 8; k++) {
            float4 a4 = *(const float4*)&sa[k][ty*4];
            float4 b4 = *(const float4*)&sb[k][tx*4];
            acc[0][0] += a4.x*b4.x; acc[0][1] += a4.x*b4.y; acc[0][2] += a4.x*b4.z; acc[0][3] += a4.x*b4.w;
            acc[1][0] += a4.y*b4.x; acc[1][1] += a4.y*b4.y; acc[1][2] += a4.y*b4.z; acc[1][3] += a4.y*b4.w;
            acc[2][0] += a4.z*b4.x; acc[2][1] += a4.z*b4.y; acc[2][2] += a4.z*b4.z; acc[2][3] += a4.z*b4.w;
            acc[3][0] += a4.w*b4.x; acc[3][1] += a4.w*b4.y; acc[3][2] += a4.w*b4.z; acc[3][3] += a4.w*b4.w;
        }
        __syncthreads();
    }
    float* dst = g_epart + (size_t)blockIdx.z * (NN*EE);
    #pragma unroll
    for (int i = 0; i < 4; i++)
        #pragma unroll
        for (int j = 0; j < 4; j++)
            dst[(rb + ty*4 + i)*EE + cb + tx*4 + j] = acc[i][j];
}

// ---------------- P1r: reduce partials + tanh(+br) ----------------
__global__ __launch_bounds__(256)
void e_reduce_kernel(const float* __restrict__ br)
{
    int i = blockIdx.x * 256 + threadIdx.x;
    float s = 0.f;
    #pragma unroll
    for (int k = 0; k < P1KS; k++) s += g_epart[(size_t)k*(NN*EE) + i];
    g_e[i] = tanhf(s + br[i & (EE-1)]);
}

// ---------------- small batched GEMM, 64x64 tile, K param, optional tanh ----
__global__ __launch_bounds__(256)
void gemm64_kernel(const float* __restrict__ A, int lda,
                   const float* __restrict__ W, int ldw,
                   const float* __restrict__ bias,
                   float* __restrict__ C, int ldc,
                   int Kd, int act)
{
    __shared__ float as[16][64];
    __shared__ float ws[16][64];
    int tid = threadIdx.x;
    int tx = tid & 15, ty = tid >> 4;
    int rb = blockIdx.y * 64, cb = blockIdx.x * 64;

    float acc[4][4];
    #pragma unroll
    for (int i = 0; i < 4; i++)
        #pragma unroll
        for (int j = 0; j < 4; j++) acc[i][j] = 0.f;

    int lr = tid >> 2, lk = (tid & 3) * 4;
    int wrw = tid >> 4, wcc = (tid & 15) * 4;

    for (int kb = 0; kb < Kd; kb += 16) {
        float4 av = *(const float4*)(A + (size_t)(rb + lr)*lda + kb + lk);
        as[lk+0][lr] = av.x; as[lk+1][lr] = av.y;
        as[lk+2][lr] = av.z; as[lk+3][lr] = av.w;
        *(float4*)&ws[wrw][wcc] = *(const float4*)(W + (size_t)(kb + wrw)*ldw + cb + wcc);
        __syncthreads();
        #pragma unroll
        for (int k = 0; k < 16; k++) {
            float4 a4 = *(const float4*)&as[k][ty*4];
            float4 b4 = *(const float4*)&ws[k][tx*4];
            acc[0][0] += a4.x*b4.x; acc[0][1] += a4.x*b4.y; acc[0][2] += a4.x*b4.z; acc[0][3] += a4.x*b4.w;
            acc[1][0] += a4.y*b4.x; acc[1][1] += a4.y*b4.y; acc[1][2] += a4.y*b4.z; acc[1][3] += a4.y*b4.w;
            acc[2][0] += a4.z*b4.x; acc[2][1] += a4.z*b4.y; acc[2][2] += a4.z*b4.z; acc[2][3] += a4.z*b4.w;
            acc[3][0] += a4.w*b4.x; acc[3][1] += a4.w*b4.y; acc[3][2] += a4.w*b4.z; acc[3][3] += a4.w*b4.w;
        }
        __syncthreads();
    }

    #pragma unroll
    for (int i = 0; i < 4; i++) {
        int row = rb + ty*4 + i;
        #pragma unroll
        for (int j = 0; j < 4; j++) {
            int col = cb + tx*4 + j;
            float v = acc[i][j] + bias[col];
            if (act) v = tanhf(v);
            C[(size_t)row*ldc + col] = v;
        }
    }
}

// ---------------- logits GEMM, 64x32 tile, K=256, mask epilogue -------------
__global__ __launch_bounds__(256)
void logits_gemm_kernel(const float* __restrict__ A /*g_hq*/,
                        const float* __restrict__ W /*wq2*/,
                        const float* __restrict__ bias,
                        const float* __restrict__ amask)
{
    __shared__ float as[16][64];
    __shared__ float ws[16][32];
    int tid = threadIdx.x;
    int tx = tid & 7, ty = tid >> 3;
    int rb = blockIdx.y * 64, cb = blockIdx.x * 32;

    float acc[2][4];
    #pragma unroll
    for (int i = 0; i < 2; i++)
        #pragma unroll
        for (int j = 0; j < 4; j++) acc[i][j] = 0.f;

    int lr = tid >> 2, lk = (tid & 3) * 4;
    int wrw = tid >> 4, wcc = (tid & 15) * 2;

    for (int kb = 0; kb < HPP; kb += 16) {
        float4 av = *(const float4*)(A + (size_t)(rb + lr)*HPP + kb + lk);
        as[lk+0][lr] = av.x; as[lk+1][lr] = av.y;
        as[lk+2][lr] = av.z; as[lk+3][lr] = av.w;
        float2 wv = *(const float2*)(W + (size_t)(kb + wrw)*LL + cb + wcc);
        ws[wrw][wcc] = wv.x; ws[wrw][wcc+1] = wv.y;
        __syncthreads();
        #pragma unroll
        for (int k = 0; k < 16; k++) {
            float2 a2 = *(const float2*)&as[k][ty*2];
            float4 b4 = *(const float4*)&ws[k][tx*4];
            acc[0][0] += a2.x*b4.x; acc[0][1] += a2.x*b4.y;
            acc[0][2] += a2.x*b4.z; acc[0][3] += a2.x*b4.w;
            acc[1][0] += a2.y*b4.x; acc[1][1] += a2.y*b4.y;
            acc[1][2] += a2.y*b4.z; acc[1][3] += a2.y*b4.w;
        }
        __syncthreads();
    }

    #pragma unroll
    for (int i = 0; i < 2; i++) {
        int row = rb + ty*2 + i;
        #pragma unroll
        for (int j = 0; j < 4; j++) {
            int col = cb + tx*4 + j;
            float v  = acc[i][j] + bias[col];
            float mk = amask[(size_t)row*LL + col];
            g_logit[(size_t)row*LL + col] = mk * (-1e6f) + v * (1.f - mk);
        }
    }
}

// ---------------- k-subset relaxation + logprob + adjacency (per sample) ----
__global__ __launch_bounds__(256)
void ksubset_kernel(const float* __restrict__ gum,
                    const float* __restrict__ adjs,
                    float* __restrict__ logp_out, int t)
{
    int n = blockIdx.x, tid = threadIdx.x;
    __shared__ float logit_s[LL];
    __shared__ float score_s[LL];
    __shared__ float sel_s  [LL];
    __shared__ float red_s  [256];

    for (int l = tid; l < LL; l += 256) {
        float a = g_logit[(size_t)n*LL + l];
        logit_s[l] = a;
        score_s[l] = a + gum[((size_t)n*TT + t)*LL + l];
        sel_s[l]   = 0.f;
    }
    __syncthreads();

    for (int it = 0; it < KK; it++) {
        for (int l = tid; l < LL; l += 256) {
            float c = 1.f - sel_s[l];
            c = fminf(fmaxf(c, 1e-6f), 1.f);
            score_s[l] += logf(c);
        }
        __syncthreads();
        float m = -1e30f;
        for (int l = tid; l < LL; l += 256) m = fmaxf(m, score_s[l]);
        m = blk_max256(m, red_s, tid);
        float ps = 0.f;
        for (int l = tid; l < LL; l += 256) ps += expf(score_s[l] - m);
        ps = blk_sum256(ps, red_s, tid);
        float inv = 1.f / ps;
        for (int l = tid; l < LL; l += 256) sel_s[l] += expf(score_s[l] - m) * inv;
        __syncthreads();
    }
    for (int l = tid; l < LL; l += 256) sel_s[l] = fminf(fmaxf(sel_s[l], 0.f), 1.f);
    __syncthreads();

    float m2 = -1e30f;
    for (int l = tid; l < LL; l += 256) m2 = fmaxf(m2, logit_s[l]);
    m2 = blk_max256(m2, red_s, tid);
    float s2 = 0.f;
    for (int l = tid; l < LL; l += 256) s2 += expf(logit_s[l] - m2);
    s2 = blk_sum256(s2, red_s, tid);
    float lse = m2 + logf(s2);
    float lp = 0.f;
    for (int l = tid; l < LL; l += 256) lp += sel_s[l] * (logit_s[l] - lse);
    lp = blk_sum256(lp, red_s, tid);
    if (tid == 0) logp_out[n*TT + t] = lp;

    for (int idx = tid; idx < DD*DD; idx += 256) {
        int i = idx / DD, j = idx % DD;
        float ctrl = 0.f;
        if (i != j) {
            int jj = (j < i) ? j : j - 1;
            ctrl = sel_s[i*(DD-1) + jj];
        }
        g_adj[(size_t)n*DD*DD + idx] = adjs[idx] * (1.f - ctrl);
    }
}

// ---------------- jump: h += tanh((adj@h)@wd + obs*wo + bd) ----------------
__global__ __launch_bounds__(256)
void jump_kernel(const float* __restrict__ wd, const float* __restrict__ bd,
                 const float* __restrict__ wo, const float* __restrict__ edata,
                 int t)
{
    int n = blockIdx.x, tid = threadIdx.x;
    __shared__ float adj_s[DD*DD];
    __shared__ float ms   [DD*HH];
    __shared__ float obs_s[DD];

    for (int i = tid; i < DD*DD; i += 256) adj_s[i] = g_adj[(size_t)n*DD*DD + i];
    if (tid < DD) obs_s[tid] = edata[((size_t)n*TT + t)*DD + tid];

    float* hn = g_h + (size_t)n * DHH;
    float hcol[DD];
    #pragma unroll
    for (int i = 0; i < DD; i++) hcol[i] = hn[i*HH + tid];
    __syncthreads();

    #pragma unroll
    for (int i = 0; i < DD; i++) {
        float a = 0.f;
        #pragma unroll
        for (int j = 0; j < DD; j++) a += adj_s[i*DD + j] * hcol[j];
        ms[i*HH + tid] = a;
    }
    __syncthreads();

    float acc[DD];
    float wot = wo[tid], bdt = bd[tid];
    #pragma unroll
    for (int i = 0; i < DD; i++) acc[i] = obs_s[i] * wot + bdt;
    for (int k = 0; k < HH; k++) {
        float w = wd[k*HH + tid];
        #pragma unroll
        for (int i = 0; i < DD; i++) acc[i] += ms[i*HH + k] * w;
    }
    #pragma unroll
    for (int i = 0; i < DD; i++) hn[i*HH + tid] = hcol[i] + tanhf(acc[i]);
}

// ---------------- fused ODE integrator + intensity, one block per sample ----
// 512 threads: 16 warps for latency hiding (ODE is LDS-latency bound at 8 warps).
// smem layout (floats): h[8192] | in[8192] | acc[8192] | t1[16384] | w[2*8192]
#define ODE_SMEM_BYTES 229376

__global__ __launch_bounds__(ONT, 1)
void ode_kernel(const float* __restrict__ wc1, const float* __restrict__ bc1,
                const float* __restrict__ wc2, const float* __restrict__ bc2,
                const float* __restrict__ wi1, const float* __restrict__ bi1,
                const float* __restrict__ wi2, const float* __restrict__ bi2,
                const float* __restrict__ et,  const float* __restrict__ t0v,
                float* __restrict__ out, int t)
{
    extern __shared__ float sm[];
    float* sh_h  = sm;
    float* sh_in = sm + 8192;
    float* sh_ac = sm + 16384;
    float* sh_t1 = sm + 24576;
    float* sh_w  = sm + 40960;     // two 8192-float buffers

    int n = blockIdx.x, tid = threadIdx.x;

    for (int i = tid; i < 8192; i += ONT) {
        int r = i >> 8;
        float v = (r < DD) ? g_h[(size_t)n*DHH + i] : 0.f;
        sh_h[i] = v; sh_in[i] = v;
    }
    float tp  = (t == 0) ? t0v[n] : et[n*TT + t - 1];
    float sdt = (et[n*TT + t] - tp) * (1.f / RKN);
    __syncthreads();

    // 512-thread tiling: 8 row-groups x 64 col-groups
    const int rg = tid >> 6;          // 0..7 -> rows rg*4 .. rg*4+3
    const int cg = tid & 63;          // column group

    for (int rk = 0; rk < RKN; rk++)
    for (int s = 0; s < 4; s++) {
        // ===== stage A: t1 = tanh(in @ wc1 + bc1)   (32x256)@(256x512)
        // per thread: 4 rows x (cols cg*4..+3 and 256+cg*4..+3) = 16 u64 accs
        {
            u64 acc2[16];
            #pragma unroll
            for (int q = 0; q < 16; q++) acc2[q] = 0ull;
            cp_tile(sh_w, wc1, 2048, tid, ONT);
            for (int kb = 0; kb < 16; kb++) {
                if (kb + 1 < 16)
                    cp_tile(sh_w + ((kb+1)&1)*8192, wc1 + (kb+1)*16*HCC, 2048, tid, ONT);
                if (kb + 1 < 16) __pipeline_wait_prior(1); else __pipeline_wait_prior(0);
                __syncthreads();
                const float* wb  = sh_w + (kb&1)*8192;
                const float* inb = sh_in + kb*16;
                #pragma unroll 4
                for (int k = 0; k < 16; k++) {
                    ulonglong2 w0 = *(const ulonglong2*)&wb[k*HCC + cg*4];
                    ulonglong2 w1 = *(const ulonglong2*)&wb[k*HCC + 256 + cg*4];
                    #pragma unroll
                    for (int i = 0; i < 4; i++) {
                        u64 aa = pk2(inb[(rg*4 + i)*HH + k]);
                        fma2(acc2[i*4+0], aa, w0.x);
                        fma2(acc2[i*4+1], aa, w0.y);
                        fma2(acc2[i*4+2], aa, w1.x);
                        fma2(acc2[i*4+3], aa, w1.y);
                    }
                }
                __syncthreads();
            }
            #pragma unroll
            for (int p = 0; p < 2; p++) {
                int c = p*256 + cg*4;
                float b0 = bc1[c], b1 = bc1[c+1], b2 = bc1[c+2], b3 = bc1[c+3];
                #pragma unroll
                for (int i = 0; i < 4; i++) {
                    float2 v0 = up2(acc2[i*4 + p*2 + 0]);
                    float2 v1 = up2(acc2[i*4 + p*2 + 1]);
                    float* dst = &sh_t1[(rg*4 + i)*HCC + c];
                    dst[0] = tanhf(v0.x + b0);
                    dst[1] = tanhf(v0.y + b1);
                    dst[2] = tanhf(v1.x + b2);
                    dst[3] = tanhf(v1.y + b3);
                }
            }
            __syncthreads();
        }
        // ===== stage B: kv = t1 @ wc2 + bc2   (32x512)@(512x256), RK epilogue
        // per thread: 4 rows x cols cg*4..+3 = 8 u64 accs
        {
            u64 acc2[8];
            #pragma unroll
            for (int q = 0; q < 8; q++) acc2[q] = 0ull;
            cp_tile(sh_w, wc2, 1024, tid, ONT);
            for (int kb = 0; kb < 32; kb++) {
                if (kb + 1 < 32)
                    cp_tile(sh_w + ((kb+1)&1)*8192, wc2 + (kb+1)*16*HH, 1024, tid, ONT);
                if (kb + 1 < 32) __pipeline_wait_prior(1); else __pipeline_wait_prior(0);
                __syncthreads();
                const float* wb = sh_w + (kb&1)*8192;
                const float* tb = sh_t1 + kb*16;
                #pragma unroll 4
                for (int k = 0; k < 16; k++) {
                    ulonglong2 w0 = *(const ulonglong2*)&wb[k*HH + cg*4];
                    #pragma unroll
                    for (int i = 0; i < 4; i++) {
                        u64 aa = pk2(tb[(rg*4 + i)*HCC + k]);
                        fma2(acc2[i*2+0], aa, w0.x);
                        fma2(acc2[i*2+1], aa, w0.y);
                    }
                }
                __syncthreads();
            }
            #pragma unroll
            for (int i = 0; i < 4; i++) {
                int r = rg*4 + i;
                int c = cg*4;
                float2 v0 = up2(acc2[i*2+0]);
                float2 v1 = up2(acc2[i*2+1]);
                float kvv[4] = { v0.x + bc2[c], v0.y + bc2[c+1],
                                 v1.x + bc2[c+2], v1.y + bc2[c+3] };
                #pragma unroll
                for (int j = 0; j < 4; j++) {
                    float kv = kvv[j];
                    int idx = r*HH + c + j;
                    if (s == 0)      { sh_ac[idx] = kv;        sh_in[idx] = sh_h[idx] + 0.5f*sdt*kv; }
                    else if (s == 1) { sh_ac[idx] += 2.f*kv;   sh_in[idx] = sh_h[idx] + 0.5f*sdt*kv; }
                    else if (s == 2) { sh_ac[idx] += 2.f*kv;   sh_in[idx] = sh_h[idx] + sdt*kv; }
                    else             { float hn = sh_h[idx] + (sdt*(1.f/6.f))*(sh_ac[idx] + kv);
                                       sh_h[idx] = hn; sh_in[idx] = hn; }
                }
            }
            __syncthreads();
        }
    }

    // write back h
    for (int i = tid; i < DHH; i += ONT) g_h[(size_t)n*DHH + i] = sh_h[i];

    // ===== intensity: softplus( tanh(h@wi1+bi1) @ wi2 + bi2 )
    // per thread: 4 rows x cols cg*2..+1 = 4 u64 accs
    {
        u64 acc2[4];
        #pragma unroll
        for (int q = 0; q < 4; q++) acc2[q] = 0ull;
        cp_tile(sh_w, wi1, 512, tid, ONT);
        for (int kb = 0; kb < 16; kb++) {
            if (kb + 1 < 16)
                cp_tile(sh_w + ((kb+1)&1)*8192, wi1 + (kb+1)*16*HII, 512, tid, ONT);
            if (kb + 1 < 16) __pipeline_wait_prior(1); else __pipeline_wait_prior(0);
            __syncthreads();
            const float* wb = sh_w + (kb&1)*8192;
            #pragma unroll 4
            for (int k = 0; k < 16; k++) {
                u64 w = *(const u64*)&wb[k*HII + cg*2];
                #pragma unroll
                for (int i = 0; i < 4; i++) {
                    u64 aa = pk2(sh_h[(rg*4 + i)*HH + kb*16 + k]);
                    fma2(acc2[i], aa, w);
                }
            }
            __syncthreads();
        }
        {
            int c = cg*2;
            float b0 = bi1[c], b1 = bi1[c+1];
            float q0 = wi2[c], q1 = wi2[c+1];
            #pragma unroll
            for (int i = 0; i < 4; i++) {
                float2 v = up2(acc2[i]);
                float* dst = &sh_t1[(rg*4 + i)*HII + c];
                dst[0] = tanhf(v.x + b0) * q0;
                dst[1] = tanhf(v.y + b1) * q1;
            }
        }
        __syncthreads();
        if (tid < DD) {
            float ssum = 0.f;
            for (int j = 0; j < HII; j++) ssum += sh_t1[tid*HII + j];
            float x = ssum + bi2[0];
            float sp = fmaxf(x, 0.f) + log1pf(expf(-fabsf(x)));
            out[((size_t)n*TT + t)*DD + tid] = sp;
        }
    }
}

// ---------------- launch ----------------
extern "C" void kernel_launch(void* const* d_in, const int* in_sizes, int n_in,
                              void* d_out, int out_size)
{
    const float* event_time = (const float*)d_in[0];
    const float* event_data = (const float*)d_in[1];
    const float* t0     = (const float*)d_in[2];
    const float* amask  = (const float*)d_in[3];
    const float* gum    = (const float*)d_in[4];
    const float* init_h = (const float*)d_in[5];
    const float* adjs   = (const float*)d_in[6];
    const float* wc1 = (const float*)d_in[7];  const float* bc1 = (const float*)d_in[8];
    const float* wc2 = (const float*)d_in[9];  const float* bc2 = (const float*)d_in[10];
    const float* wd  = (const float*)d_in[11]; const float* bd  = (const float*)d_in[12];
    const float* wo  = (const float*)d_in[13];
    const float* wi1 = (const float*)d_in[14]; const float* bi1 = (const float*)d_in[15];
    const float* wi2 = (const float*)d_in[16]; const float* bi2 = (const float*)d_in[17];
    const float* wr  = (const float*)d_in[18]; const float* br  = (const float*)d_in[19];
    const float* wp  = (const float*)d_in[20]; const float* bp  = (const float*)d_in[21];
    const float* wm  = (const float*)d_in[22]; const float* bm  = (const float*)d_in[23];
    const float* wq1 = (const float*)d_in[24]; const float* bq1 = (const float*)d_in[25];
    const float* wq2 = (const float*)d_in[26]; const float* bq2 = (const float*)d_in[27];

    float* out      = (float*)d_out;
    float* out_logp = out + (size_t)NN*TT*DD;

    void* p;
    cudaGetSymbolAddress(&p, g_e);     float* e_ptr   = (float*)p;
    cudaGetSymbolAddress(&p, g_cat);   float* cat_ptr = (float*)p;
    cudaGetSymbolAddress(&p, g_hq);    float* hq_ptr  = (float*)p;

    cudaFuncSetAttribute(ode_kernel, cudaFuncAttributeMaxDynamicSharedMemorySize,
                         ODE_SMEM_BYTES);

    init_h_kernel<<<(NN*DHH + 255)/256, 256>>>(init_h);

    for (int t = 0; t < TT; t++) {
        e_gemm_kernel<<<dim3(2, 2, P1KS), 256>>>(wr);
        e_reduce_kernel<<<(NN*EE)/256, 256>>>(br);
        gemm64_kernel<<<dim3(2, 2), 256>>>(e_ptr, EE, wp, EE, bp,
                                           cat_ptr, 2*EE, EE, 0);
        gemm64_kernel<<<dim3(2, 2), 256>>>(e_ptr, EE, wm, EE, bm,
                                           cat_ptr + EE, 2*EE, EE, 0);
        gemm64_kernel<<<dim3(4, 2), 256>>>(cat_ptr, 2*EE, wq1, HPP, bq1,
                                           hq_ptr, HPP, 2*EE, 1);
        logits_gemm_kernel<<<dim3(LL/32, 2), 256>>>(hq_ptr, wq2, bq2, amask);
        ksubset_kernel<<<NN, 256>>>(gum, adjs, out_logp, t);
        jump_kernel<<<NN, 256>>>(wd, bd, wo, event_data, t);
        ode_kernel<<<NN, ONT, ODE_SMEM_BYTES>>>(wc1, bc1, wc2, bc2,
                                                wi1, bi1, wi2, bi2,
                                                event_time, t0, out, t);
    }
}